// round 13
// baseline (speedup 1.0000x reference)
#include <cuda_runtime.h>
#include <math.h>

// B=8, IC=8, IND=16, MID=32, OC=8, OD=16, H=W=64, HW=4096, ITERS=3

// -------- scratch (device globals) --------
__device__ float g_h1[8 * 256 * 4096];            // [B][IC*MID][H*W]
__device__ float g_h2[8 * 256 * 4096];            // [B][IC*MID][H*W]
__device__ float g_w3t[8 * 32 * 128];             // transposed w3: [ic][ch][j]
__device__ float g_s[(size_t)32768 * 128];        // pixel-major [B*HW][OC*OD]
__device__ float g_part[8 * 128 * 128];
__device__ float g_meanhw[8 * 128];
__device__ float g_avg[8 * 8 * 4096];
__device__ float g_stats[8 * 8 * 2];

typedef unsigned long long u64;

__device__ __forceinline__ u64 fma2(u64 a, u64 b, u64 c) {
    u64 d;
    asm("fma.rn.f32x2 %0, %1, %2, %3;" : "=l"(d) : "l"(a), "l"(b), "l"(c));
    return d;
}
__device__ __forceinline__ u64 pack2(float lo, float hi) {
    u64 d;
    asm("mov.b64 %0, {%1, %2};" : "=l"(d) : "f"(lo), "f"(hi));
    return d;
}
__device__ __forceinline__ void unpack2(u64 v, float& lo, float& hi) {
    asm("mov.b64 {%0, %1}, %2;" : "=f"(lo), "=f"(hi) : "l"(v));
}
__device__ __forceinline__ float squash_factor(float sq) {
    return sq / (0.5f + sq) / (sqrtf(sq + 1e-6f) + 1e-6f);
}
__device__ __forceinline__ float sigmoidf_(float z) {
    return 1.0f / (1.0f + __expf(-z));
}

// ================= K1: relu(x) -> grouped 1x1 (16->32) -> relu (f32x2) =========
__global__ void __launch_bounds__(256) k1_conv1(const float* __restrict__ x,
                                                const float* __restrict__ w1,
                                                const float* __restrict__ b1) {
    int blk = blockIdx.x;
    int chunk = blk & 7;
    int g = (blk >> 3) & 7;
    int b = blk >> 6;
    __shared__ u64 ws2[512];
    __shared__ float bs[32];
    int t = threadIdx.x;
    {
        float w = w1[g * 512 + t];
        ws2[t] = pack2(w, w);
        w = w1[g * 512 + t + 256];
        ws2[t + 256] = pack2(w, w);
        if (t < 32) bs[t] = b1[g * 32 + t];
    }
    __syncthreads();

    int p0 = chunk * 512 + 2 * t;
    const float* xp = x + ((size_t)b * 128 + g * 16) * 4096 + p0;
    u64 acc[32];
#pragma unroll
    for (int m = 0; m < 32; m++) acc[m] = pack2(bs[m], bs[m]);
#pragma unroll
    for (int i = 0; i < 16; i++) {
        float2 xv = *(const float2*)(xp + (size_t)i * 4096);
        u64 xpair = pack2(fmaxf(xv.x, 0.f), fmaxf(xv.y, 0.f));
#pragma unroll
        for (int m = 0; m < 32; m++) acc[m] = fma2(ws2[m * 16 + i], xpair, acc[m]);
    }
    float* op = g_h1 + ((size_t)b * 256 + g * 32) * 4096 + p0;
#pragma unroll
    for (int m = 0; m < 32; m++) {
        float lo, hi;
        unpack2(acc[m], lo, hi);
        float2 o = make_float2(fmaxf(lo, 0.f), fmaxf(hi, 0.f));
        *(float2*)(op + (size_t)m * 4096) = o;
    }
}

// ================= K2: grouped 3x3 SAME (32->32) -> relu (f32x2) ==============
// R11 form (best measured: 162.5us). grid 1024 = B*IC*16 row-stripes of 4 rows.
// 256 threads = 8 ocg x 32 lanes; 4 oc x 8 px per thread. Weights staged once
// as plain floats; input channels in 4 chunks of 8, division-free staging.
__device__ __forceinline__ int slot_phys(int s) { return s + (s >> 4); }
#define K2_W_BYTES (9216 * 4)                  // 36864
#define K2_IN_BYTES (8 * 6 * 71 * 8)           // 27264
#define SMEM_K2 (K2_W_BYTES + K2_IN_BYTES)     // 64128

__global__ void __launch_bounds__(256, 3) k2_conv3(const float* __restrict__ w2,
                                                   const float* __restrict__ b2) {
    extern __shared__ char dsm2[];
    float* wsF = (float*)dsm2;                 // [32oc][32ic][9]
    u64* in2 = (u64*)(dsm2 + K2_W_BYTES);      // [8ch][6r][71 slots]

    int id = blockIdx.x;
    int ys = id & 15, g = (id >> 4) & 7, b = id >> 7;
    int y0 = ys * 4;
    int t = threadIdx.x;
    int ocg = t >> 5;                          // 0..7 (warp-uniform); also ch for staging
    int lane = t & 31;
    int row = lane >> 3;                       // 0..3
    int xseg = lane & 7;
    int x0 = 8 * xseg;

    for (int idx = t; idx < 9216; idx += 256) wsF[idx] = w2[g * 9216 + idx];

    int voff[9];
#pragma unroll
    for (int k = 0; k < 9; k++) voff[k] = slot_phys(x0 + k);

    u64 acc[4][4];
#pragma unroll
    for (int j = 0; j < 4; j++)
#pragma unroll
        for (int i = 0; i < 4; i++) acc[j][i] = 0ULL;

    const size_t hbase = ((size_t)b * 256 + g * 32) * 4096;

    for (int c0 = 0; c0 < 32; c0 += 8) {
        __syncthreads();
        {
            int ch = ocg;
            const float* src = g_h1 + hbase + (size_t)(c0 + ch) * 4096;
            u64* dst = in2 + ch * 6 * 71;
#pragma unroll
            for (int r = 0; r < 6; r++) {
                int gy = y0 + r - 1;
                bool okr = (unsigned)gy < 64u;
                const float* rp = src + gy * 64;
                float lo, hi;
                lo = (okr && lane >= 1) ? rp[lane - 1] : 0.f;
                hi = okr ? rp[lane] : 0.f;
                dst[r * 71 + slot_phys(lane)] = pack2(lo, hi);
                lo = okr ? rp[lane + 31] : 0.f;
                hi = okr ? rp[lane + 32] : 0.f;
                dst[r * 71 + slot_phys(lane + 32)] = pack2(lo, hi);
                if (lane == 0) {
                    lo = okr ? rp[63] : 0.f;
                    dst[r * 71 + slot_phys(64)] = pack2(lo, 0.f);
                }
            }
        }
        __syncthreads();

#pragma unroll
        for (int ic = 0; ic < 8; ic++) {
            int icg = c0 + ic;
#pragma unroll
            for (int r = 0; r < 3; r++) {
                const u64* vp = in2 + (ic * 6 + row + r) * 71;
                u64 v[9];
#pragma unroll
                for (int k = 0; k < 9; k++) v[k] = vp[voff[k]];
#pragma unroll
                for (int j = 0; j < 4; j++) {
                    const float* wp = wsF + ((ocg * 4 + j) * 32 + icg) * 9 + r * 3;
#pragma unroll
                    for (int kx = 0; kx < 3; kx++) {
                        u64 w = pack2(wp[kx], wp[kx]);
#pragma unroll
                        for (int i = 0; i < 4; i++)
                            acc[j][i] = fma2(w, v[2 * i + kx], acc[j][i]);
                    }
                }
            }
        }
    }
#pragma unroll
    for (int j = 0; j < 4; j++) {
        int oc = ocg * 4 + j;
        float bv = b2[g * 32 + oc];
        float* op = g_h2 + hbase + (size_t)oc * 4096 + (y0 + row) * 64 + x0;
#pragma unroll
        for (int i = 0; i < 2; i++) {
            float a, bq, c, d;
            unpack2(acc[j][2 * i], a, bq);
            unpack2(acc[j][2 * i + 1], c, d);
            float4 o = make_float4(fmaxf(a + bv, 0.f), fmaxf(bq + bv, 0.f),
                                   fmaxf(c + bv, 0.f), fmaxf(d + bv, 0.f));
            *(float4*)(op + 4 * i) = o;
        }
    }
}

// ================= KW3T: transpose w3 -> [ic][ch][j] (j-major pairs) ===========
__global__ void __launch_bounds__(256) kw3t(const float* __restrict__ w3) {
    int idx = blockIdx.x * 256 + threadIdx.x;  // 32768 total
    int ic = idx >> 12;
    int ch = (idx >> 7) & 31;
    int j = idx & 127;
    g_w3t[idx] = w3[((size_t)ic * 128 + j) * 32 + ch];
}

// ================= K34: fused grouped 1x1 (32->128) + squash + routing =========
// 512 thr, 64 px per block, grid 512. 16 warps = (half h, ic). Per qq:
// stage j-major weight pairs (32KB, amortized over 64 px); Phase A: warp=(ic,h),
// lane=pixel; Phase B: warp=4 px, lane=(ic,r), sequential over the 2 oc's
// (halves peak regs in the shuffle section -> fits 64-reg budget, 2 blocks/SM).
#define UH_ROW 292
#define SMEM34 (32768 + 64 * UH_ROW * 4)       // 107520

__global__ void __launch_bounds__(512, 2) k34_fused(const float* __restrict__ b3) {
    extern __shared__ char dsm[];
    u64* wsm = (u64*)dsm;                     // [8 ic][32 ch][16 jpair]
    float* uh = (float*)(dsm + 32768);        // [64 px][UH_ROW]

    int blk = blockIdx.x;
    int chunk = blk & 63, b = blk >> 6;
    int px0 = chunk * 64;
    int t = threadIdx.x;
    int w = t >> 5, lane = t & 31;

    // Phase A ids: warp = (h, ic)
    int icA = w & 7, h = w >> 3;
    int pA = h * 32 + lane;                   // pixel-in-block 0..63

    // Phase B ids
    int icb = lane >> 2;
    int r = lane & 3;
    int pxl = 4 * w + r;                      // 0..63
    int pixelb = b * 4096 + px0 + pxl;

    const float* hA = g_h2 + ((size_t)b * 256 + icA * 32) * 4096 + px0 + pA;
    const u64* w3t64 = (const u64*)g_w3t;

    for (int qq = 0; qq < 4; qq++) {
        __syncthreads();
        // ---- stage weight pairs for this j-slice ----
        for (int idx = t; idx < 4096; idx += 512) {
            int ic2 = idx >> 9;
            int rem = idx & 511;
            int ch = rem >> 4;
            int jp = rem & 15;
            wsm[idx] = w3t64[ic2 * 2048 + ch * 64 + qq * 16 + jp];
        }
        __syncthreads();

        // ---- Phase A: GEMM, 1 px per lane, 16 j-pairs ----
        {
            u64 acc2[16];
            const u64* bsrc = (const u64*)(b3 + icA * 128 + qq * 32);
#pragma unroll
            for (int jp = 0; jp < 16; jp++) acc2[jp] = __ldg(&bsrc[jp]);
#pragma unroll
            for (int ch4 = 0; ch4 < 8; ch4++) {
#pragma unroll
                for (int cc = 0; cc < 4; cc++) {
                    int ch = ch4 * 4 + cc;
                    float hv = hA[(size_t)ch * 4096];
                    u64 hb = pack2(hv, hv);
                    const u64* wrow = wsm + icA * 512 + ch * 16;
#pragma unroll
                    for (int jp2 = 0; jp2 < 8; jp2++) {
                        ulonglong2 ww = *(const ulonglong2*)(wrow + 2 * jp2);
                        acc2[2 * jp2] = fma2(ww.x, hb, acc2[2 * jp2]);
                        acc2[2 * jp2 + 1] = fma2(ww.y, hb, acc2[2 * jp2 + 1]);
                    }
                }
            }
            float* d = uh + pA * UH_ROW + icA * 36;
#pragma unroll
            for (int m = 0; m < 8; m++) {
                float j0, j1, j2, j3;
                unpack2(acc2[2 * m], j0, j1);
                unpack2(acc2[2 * m + 1], j2, j3);
                *(float4*)(d + 4 * m) = make_float4(j0, j1, j2, j3);
            }
        }
        __syncthreads();

        // ---- Phase B: routing, sequential over the two oc's of this pair ----
#pragma unroll
        for (int oc01 = 0; oc01 < 2; oc01++) {
            const float* ub = uh + pxl * UH_ROW + icb * 36 + oc01 * 16;
            float u0[16];
#pragma unroll
            for (int m = 0; m < 4; m++) {
                float4 v = *(const float4*)(ub + 4 * m);
                u0[4 * m] = v.x; u0[4 * m + 1] = v.y;
                u0[4 * m + 2] = v.z; u0[4 * m + 3] = v.w;
            }
            float sq0 = 0.f;
#pragma unroll
            for (int od = 0; od < 16; od++) sq0 += u0[od] * u0[od];
            float f0 = squash_factor(sq0);
            float b0 = 0.f;
            float t0[16];

#pragma unroll
            for (int it = 0; it < 2; it++) {
                float w0 = f0 * sigmoidf_(b0);
#pragma unroll
                for (int od = 0; od < 16; od++) t0[od] = w0 * u0[od];
#pragma unroll
                for (int d = 4; d <= 16; d <<= 1) {
#pragma unroll
                    for (int od = 0; od < 16; od++)
                        t0[od] += __shfl_xor_sync(0xFFFFFFFFu, t0[od], d);
                }
                float gs0 = 0.f, dot0 = 0.f;
#pragma unroll
                for (int od = 0; od < 16; od++) {
                    gs0 += t0[od] * t0[od];
                    dot0 += u0[od] * t0[od];
                }
                b0 += f0 * squash_factor(gs0) * dot0;
            }
            {
                float w0 = sigmoidf_(b0);
#pragma unroll
                for (int od = 0; od < 16; od++) t0[od] = w0 * u0[od];
#pragma unroll
                for (int d = 4; d <= 16; d <<= 1) {
#pragma unroll
                    for (int od = 0; od < 16; od++)
                        t0[od] += __shfl_xor_sync(0xFFFFFFFFu, t0[od], d);
                }
            }
            float a0 = 0.f, a1 = 0.f;
#pragma unroll
            for (int k = 0; k < 8; k++) {
                if (icb == k) { a0 = t0[2 * k]; a1 = t0[2 * k + 1]; }
            }
            *(float2*)(g_s + (size_t)pixelb * 128 + (qq * 2 + oc01) * 16 + 2 * icb) =
                make_float2(a0, a1);
        }
    }
}

// ================= K5a/K5b: mean over HW (two-stage, deterministic) ============
__global__ void __launch_bounds__(128) k5a() {
    int id = blockIdx.x;
    int chunk = id & 127, b = id >> 7;
    int t = threadIdx.x;
    float acc = 0.f;
    const float* sp = g_s + ((size_t)(b * 4096 + chunk * 32)) * 128 + t;
    for (int p = 0; p < 32; p++) acc += sp[(size_t)p * 128];
    g_part[(b * 128 + chunk) * 128 + t] = acc;
}
__global__ void __launch_bounds__(128) k5b() {
    int b = blockIdx.x, t = threadIdx.x;
    float acc = 0.f;
    for (int c = 0; c < 128; c++) acc += g_part[(b * 128 + c) * 128 + t];
    g_meanhw[b * 128 + t] = acc * (1.0f / 4096.0f);
}

// ================= K6: avg + per-(b,oc) mean/std over HW =======================
__global__ void __launch_bounds__(256) k6() {
    int b = blockIdx.x >> 3, oc = blockIdx.x & 7;
    int t = threadIdx.x;
    __shared__ float mh[16];
    __shared__ double red[512];
    if (t < 16) mh[t] = g_meanhw[b * 128 + oc * 16 + t];
    __syncthreads();
    float mhl[16];
#pragma unroll
    for (int od = 0; od < 16; od++) mhl[od] = mh[od];

    double sum = 0.0, ssum = 0.0;
    for (int p = t; p < 4096; p += 256) {
        const float4* sp =
            (const float4*)(g_s + ((size_t)(b * 4096 + p)) * 128 + oc * 16);
        float a = 0.f;
#pragma unroll
        for (int j = 0; j < 4; j++) {
            float4 v = sp[j];
            a += v.x * mhl[4 * j] + v.y * mhl[4 * j + 1] + v.z * mhl[4 * j + 2] +
                 v.w * mhl[4 * j + 3];
        }
        g_avg[(b * 8 + oc) * 4096 + p] = a;
        sum += (double)a;
        ssum += (double)a * (double)a;
    }
    red[t] = sum;
    red[256 + t] = ssum;
    __syncthreads();
    for (int st = 128; st > 0; st >>= 1) {
        if (t < st) {
            red[t] += red[t + st];
            red[256 + t] += red[256 + t + st];
        }
        __syncthreads();
    }
    if (t == 0) {
        double S = red[0], Q = red[256];
        double m = S / 4096.0;
        double var = (Q - S * m) / 4095.0;
        if (var < 0.0) var = 0.0;
        g_stats[(b * 8 + oc) * 2] = (float)m;
        g_stats[(b * 8 + oc) * 2 + 1] = (float)(sqrt(var) + 1e-6);
    }
}

// ================= K7: out = s*sigmoid(norm*aw+ab) + x (planar) ===============
__global__ void __launch_bounds__(256) k7(const float* __restrict__ x,
                                          const float* __restrict__ aw,
                                          const float* __restrict__ ab,
                                          float* __restrict__ out) {
    int id = blockIdx.x;
    int tile = id & 63, b = id >> 6;
    int pixbase = tile * 64;
    __shared__ float ssh[64 * 129];
    __shared__ float stm[8], sts[8], awl[8], abl[8];
    int t = threadIdx.x;
    if (t < 8) {
        stm[t] = g_stats[(b * 8 + t) * 2];
        sts[t] = g_stats[(b * 8 + t) * 2 + 1];
        awl[t] = aw[t];
        abl[t] = ab[t];
    }
    for (int idx = t; idx < 8192; idx += 256) {
        int p = idx >> 7, c = idx & 127;
        ssh[p * 129 + c] = g_s[((size_t)(b * 4096 + pixbase + p)) * 128 + c];
    }
    __syncthreads();
    int cs = t >> 6, p = t & 63;
    for (int k = 0; k < 32; k++) {
        int c = k * 4 + cs;
        int oc = c >> 4;
        float a = g_avg[(b * 8 + oc) * 4096 + pixbase + p];
        float tn = (a - stm[oc]) / sts[oc] * awl[oc] + abl[oc];
        float sg = sigmoidf_(tn);
        size_t o = ((size_t)(b * 128 + c)) * 4096 + pixbase + p;
        out[o] = ssh[p * 129 + c] * sg + x[o];
    }
}

// ================= launcher =================
extern "C" void kernel_launch(void* const* d_in, const int* in_sizes, int n_in,
                              void* d_out, int out_size) {
    const float* x = (const float*)d_in[0];
    const float* w1 = (const float*)d_in[1];
    const float* b1 = (const float*)d_in[2];
    const float* w2 = (const float*)d_in[3];
    const float* b2 = (const float*)d_in[4];
    const float* w3 = (const float*)d_in[5];
    const float* b3 = (const float*)d_in[6];
    const float* aw = (const float*)d_in[7];
    const float* ab = (const float*)d_in[8];
    float* out = (float*)d_out;

    static int smem_set = 0;
    if (!smem_set) {
        cudaFuncSetAttribute(k2_conv3, cudaFuncAttributeMaxDynamicSharedMemorySize,
                             SMEM_K2);
        cudaFuncSetAttribute(k34_fused, cudaFuncAttributeMaxDynamicSharedMemorySize,
                             SMEM34);
        smem_set = 1;
    }

    k1_conv1<<<512, 256>>>(x, w1, b1);
    kw3t<<<128, 256>>>(w3);
    k2_conv3<<<1024, 256, SMEM_K2>>>(w2, b2);
    k34_fused<<<512, 512, SMEM34>>>(b3);        // <- ncu capture slot (#4)
    k5a<<<1024, 128>>>();
    k5b<<<8, 128>>>();
    k6<<<64, 256>>>();
    k7<<<512, 256>>>(x, aw, ab, out);
}

// round 14
// speedup vs baseline: 1.0953x; 1.0953x over previous
#include <cuda_runtime.h>
#include <math.h>

// B=8, IC=8, IND=16, MID=32, OC=8, OD=16, H=W=64, HW=4096, ITERS=3

// -------- scratch (device globals) --------
__device__ float g_h1[8 * 256 * 4096];            // [B][IC*MID][H*W]
__device__ float g_h2[8 * 256 * 4096];            // [B][IC*MID][H*W]
__device__ float g_w3t[8 * 32 * 128];             // qq-major w3: [qq][ic][ch][32j]
__device__ float g_s[(size_t)32768 * 128];        // pixel-major [B*HW][OC*OD]
__device__ float g_part[8 * 128 * 128];
__device__ float g_meanhw[8 * 128];
__device__ float g_avg[8 * 8 * 4096];
__device__ float g_stats[8 * 8 * 2];

typedef unsigned long long u64;

__device__ __forceinline__ u64 fma2(u64 a, u64 b, u64 c) {
    u64 d;
    asm("fma.rn.f32x2 %0, %1, %2, %3;" : "=l"(d) : "l"(a), "l"(b), "l"(c));
    return d;
}
__device__ __forceinline__ u64 pack2(float lo, float hi) {
    u64 d;
    asm("mov.b64 %0, {%1, %2};" : "=l"(d) : "f"(lo), "f"(hi));
    return d;
}
__device__ __forceinline__ void unpack2(u64 v, float& lo, float& hi) {
    asm("mov.b64 {%0, %1}, %2;" : "=f"(lo), "=f"(hi) : "l"(v));
}
__device__ __forceinline__ float squash_factor(float sq) {
    return sq / (0.5f + sq) / (sqrtf(sq + 1e-6f) + 1e-6f);
}
__device__ __forceinline__ float sigmoidf_(float z) {
    return 1.0f / (1.0f + __expf(-z));
}

// ================= K1: relu(x) -> grouped 1x1 (16->32) -> relu (f32x2) =========
__global__ void __launch_bounds__(256) k1_conv1(const float* __restrict__ x,
                                                const float* __restrict__ w1,
                                                const float* __restrict__ b1) {
    int blk = blockIdx.x;
    int chunk = blk & 7;
    int g = (blk >> 3) & 7;
    int b = blk >> 6;
    __shared__ u64 ws2[512];
    __shared__ float bs[32];
    int t = threadIdx.x;
    {
        float w = w1[g * 512 + t];
        ws2[t] = pack2(w, w);
        w = w1[g * 512 + t + 256];
        ws2[t + 256] = pack2(w, w);
        if (t < 32) bs[t] = b1[g * 32 + t];
    }
    __syncthreads();

    int p0 = chunk * 512 + 2 * t;
    const float* xp = x + ((size_t)b * 128 + g * 16) * 4096 + p0;
    u64 acc[32];
#pragma unroll
    for (int m = 0; m < 32; m++) acc[m] = pack2(bs[m], bs[m]);
#pragma unroll
    for (int i = 0; i < 16; i++) {
        float2 xv = *(const float2*)(xp + (size_t)i * 4096);
        u64 xpair = pack2(fmaxf(xv.x, 0.f), fmaxf(xv.y, 0.f));
#pragma unroll
        for (int m = 0; m < 32; m++) acc[m] = fma2(ws2[m * 16 + i], xpair, acc[m]);
    }
    float* op = g_h1 + ((size_t)b * 256 + g * 32) * 4096 + p0;
#pragma unroll
    for (int m = 0; m < 32; m++) {
        float lo, hi;
        unpack2(acc[m], lo, hi);
        float2 o = make_float2(fmaxf(lo, 0.f), fmaxf(hi, 0.f));
        *(float2*)(op + (size_t)m * 4096) = o;
    }
}

// ================= K2: grouped 3x3 SAME (32->32) -> relu (f32x2) ==============
// R11 form (best measured: 162.5us).
__device__ __forceinline__ int slot_phys(int s) { return s + (s >> 4); }
#define K2_W_BYTES (9216 * 4)                  // 36864
#define K2_IN_BYTES (8 * 6 * 71 * 8)           // 27264
#define SMEM_K2 (K2_W_BYTES + K2_IN_BYTES)     // 64128

__global__ void __launch_bounds__(256, 3) k2_conv3(const float* __restrict__ w2,
                                                   const float* __restrict__ b2) {
    extern __shared__ char dsm2[];
    float* wsF = (float*)dsm2;                 // [32oc][32ic][9]
    u64* in2 = (u64*)(dsm2 + K2_W_BYTES);      // [8ch][6r][71 slots]

    int id = blockIdx.x;
    int ys = id & 15, g = (id >> 4) & 7, b = id >> 7;
    int y0 = ys * 4;
    int t = threadIdx.x;
    int ocg = t >> 5;
    int lane = t & 31;
    int row = lane >> 3;
    int xseg = lane & 7;
    int x0 = 8 * xseg;

    for (int idx = t; idx < 9216; idx += 256) wsF[idx] = w2[g * 9216 + idx];

    int voff[9];
#pragma unroll
    for (int k = 0; k < 9; k++) voff[k] = slot_phys(x0 + k);

    u64 acc[4][4];
#pragma unroll
    for (int j = 0; j < 4; j++)
#pragma unroll
        for (int i = 0; i < 4; i++) acc[j][i] = 0ULL;

    const size_t hbase = ((size_t)b * 256 + g * 32) * 4096;

    for (int c0 = 0; c0 < 32; c0 += 8) {
        __syncthreads();
        {
            int ch = ocg;
            const float* src = g_h1 + hbase + (size_t)(c0 + ch) * 4096;
            u64* dst = in2 + ch * 6 * 71;
#pragma unroll
            for (int r = 0; r < 6; r++) {
                int gy = y0 + r - 1;
                bool okr = (unsigned)gy < 64u;
                const float* rp = src + gy * 64;
                float lo, hi;
                lo = (okr && lane >= 1) ? rp[lane - 1] : 0.f;
                hi = okr ? rp[lane] : 0.f;
                dst[r * 71 + slot_phys(lane)] = pack2(lo, hi);
                lo = okr ? rp[lane + 31] : 0.f;
                hi = okr ? rp[lane + 32] : 0.f;
                dst[r * 71 + slot_phys(lane + 32)] = pack2(lo, hi);
                if (lane == 0) {
                    lo = okr ? rp[63] : 0.f;
                    dst[r * 71 + slot_phys(64)] = pack2(lo, 0.f);
                }
            }
        }
        __syncthreads();

#pragma unroll
        for (int ic = 0; ic < 8; ic++) {
            int icg = c0 + ic;
#pragma unroll
            for (int r = 0; r < 3; r++) {
                const u64* vp = in2 + (ic * 6 + row + r) * 71;
                u64 v[9];
#pragma unroll
                for (int k = 0; k < 9; k++) v[k] = vp[voff[k]];
#pragma unroll
                for (int j = 0; j < 4; j++) {
                    const float* wp = wsF + ((ocg * 4 + j) * 32 + icg) * 9 + r * 3;
#pragma unroll
                    for (int kx = 0; kx < 3; kx++) {
                        u64 w = pack2(wp[kx], wp[kx]);
#pragma unroll
                        for (int i = 0; i < 4; i++)
                            acc[j][i] = fma2(w, v[2 * i + kx], acc[j][i]);
                    }
                }
            }
        }
    }
#pragma unroll
    for (int j = 0; j < 4; j++) {
        int oc = ocg * 4 + j;
        float bv = b2[g * 32 + oc];
        float* op = g_h2 + hbase + (size_t)oc * 4096 + (y0 + row) * 64 + x0;
#pragma unroll
        for (int i = 0; i < 2; i++) {
            float a, bq, c, d;
            unpack2(acc[j][2 * i], a, bq);
            unpack2(acc[j][2 * i + 1], c, d);
            float4 o = make_float4(fmaxf(a + bv, 0.f), fmaxf(bq + bv, 0.f),
                                   fmaxf(c + bv, 0.f), fmaxf(d + bv, 0.f));
            *(float4*)(op + 4 * i) = o;
        }
    }
}

// ================= KW3T: w3 -> qq-major [qq][ic][ch][32j] =====================
__global__ void __launch_bounds__(256) kw3t(const float* __restrict__ w3) {
    int idx = blockIdx.x * 256 + threadIdx.x;  // 32768 total
    int jj = idx & 31;
    int ch = (idx >> 5) & 31;
    int ic = (idx >> 10) & 7;
    int qq = idx >> 13;
    g_w3t[idx] = w3[((size_t)ic * 128 + qq * 32 + jj) * 32 + ch];
}

// ================= K34: fused grouped 1x1 (32->128) + squash + routing =========
// 256 thr, 32 px per block, grid 1024. Per qq:
//  stage scalar weight slice (32KB contiguous copy).
//  Phase A: warp=ic, lane=(jg 4, pg 8): 4 px x 8 j per lane -> weight LDS
//  amortized over 4 pixels (256->64 LDS.128 per thread per qq).
//  Phase B: warp=4 px, lane=(ic,r), interleaved 2-oc chains (R12 form).
#define UH_ROW 292
#define SMEM34 (32768 + 32 * UH_ROW * 4)

__global__ void __launch_bounds__(256, 3) k34_fused(const float* __restrict__ b3) {
    extern __shared__ char dsm[];
    float* wsm = (float*)dsm;                 // [8 ic][32 ch][32 j] floats
    float* uh = (float*)(dsm + 32768);        // [32 px][UH_ROW]

    int blk = blockIdx.x;
    int chunk = blk & 127, b = blk >> 7;
    int px0 = chunk * 32;
    int t = threadIdx.x;
    int w = t >> 5, lane = t & 31;
    int jg = lane >> 3;                       // 0..3 -> j0 = jg*8
    int pg = lane & 7;                        // 0..7 -> px = pg*4..+3

    // Phase B ids
    int icb = lane >> 2;
    int r = lane & 3;
    int pxl = 4 * w + r;
    int pixelb = b * 4096 + px0 + pxl;

    const float* hA4 = g_h2 + ((size_t)b * 256 + w * 32) * 4096 + px0 + pg * 4;

    for (int qq = 0; qq < 4; qq++) {
        __syncthreads();
        // ---- stage scalar weight slice: contiguous 32KB ----
        {
            const float4* src = (const float4*)(g_w3t + qq * 8192);
            float4* dst = (float4*)wsm;
            for (int idx = t; idx < 2048; idx += 256) dst[idx] = src[idx];
        }
        __syncthreads();

        // ---- Phase A: 4 px x 8 j per lane ----
        {
            u64 acc[8][2];
#pragma unroll
            for (int j = 0; j < 8; j++) {
                float bv = __ldg(&b3[w * 128 + qq * 32 + jg * 8 + j]);
                acc[j][0] = pack2(bv, bv);
                acc[j][1] = acc[j][0];
            }
            const float* wbase = wsm + (w * 32) * 32 + jg * 8;
#pragma unroll
            for (int ch = 0; ch < 32; ch++) {
                float4 hv = *(const float4*)(hA4 + (size_t)ch * 4096);
                u64 hp0 = pack2(hv.x, hv.y), hp1 = pack2(hv.z, hv.w);
                float4 wa = *(const float4*)(wbase + ch * 32);
                float4 wb = *(const float4*)(wbase + ch * 32 + 4);
                u64 wd;
                wd = pack2(wa.x, wa.x);
                acc[0][0] = fma2(wd, hp0, acc[0][0]);
                acc[0][1] = fma2(wd, hp1, acc[0][1]);
                wd = pack2(wa.y, wa.y);
                acc[1][0] = fma2(wd, hp0, acc[1][0]);
                acc[1][1] = fma2(wd, hp1, acc[1][1]);
                wd = pack2(wa.z, wa.z);
                acc[2][0] = fma2(wd, hp0, acc[2][0]);
                acc[2][1] = fma2(wd, hp1, acc[2][1]);
                wd = pack2(wa.w, wa.w);
                acc[3][0] = fma2(wd, hp0, acc[3][0]);
                acc[3][1] = fma2(wd, hp1, acc[3][1]);
                wd = pack2(wb.x, wb.x);
                acc[4][0] = fma2(wd, hp0, acc[4][0]);
                acc[4][1] = fma2(wd, hp1, acc[4][1]);
                wd = pack2(wb.y, wb.y);
                acc[5][0] = fma2(wd, hp0, acc[5][0]);
                acc[5][1] = fma2(wd, hp1, acc[5][1]);
                wd = pack2(wb.z, wb.z);
                acc[6][0] = fma2(wd, hp0, acc[6][0]);
                acc[6][1] = fma2(wd, hp1, acc[6][1]);
                wd = pack2(wb.w, wb.w);
                acc[7][0] = fma2(wd, hp0, acc[7][0]);
                acc[7][1] = fma2(wd, hp1, acc[7][1]);
            }
            // store to uh: 4 px x 8 j
#pragma unroll
            for (int p = 0; p < 4; p++) {
                float v[8];
#pragma unroll
                for (int j = 0; j < 8; j++) {
                    float lo, hi;
                    unpack2(acc[j][p >> 1], lo, hi);
                    v[j] = (p & 1) ? hi : lo;
                }
                float* d = uh + (pg * 4 + p) * UH_ROW + w * 36 + jg * 8;
                *(float4*)d = make_float4(v[0], v[1], v[2], v[3]);
                *(float4*)(d + 4) = make_float4(v[4], v[5], v[6], v[7]);
            }
        }
        __syncthreads();

        // ---- Phase B: routing for oc pair (2qq, 2qq+1), interleaved ----
        {
            const float* ub = uh + pxl * UH_ROW + icb * 36;
            float u0[16], u1[16];
#pragma unroll
            for (int m = 0; m < 4; m++) {
                float4 v = *(const float4*)(ub + 4 * m);
                u0[4 * m] = v.x; u0[4 * m + 1] = v.y;
                u0[4 * m + 2] = v.z; u0[4 * m + 3] = v.w;
            }
#pragma unroll
            for (int m = 0; m < 4; m++) {
                float4 v = *(const float4*)(ub + 16 + 4 * m);
                u1[4 * m] = v.x; u1[4 * m + 1] = v.y;
                u1[4 * m + 2] = v.z; u1[4 * m + 3] = v.w;
            }
            float sq0 = 0.f, sq1 = 0.f;
#pragma unroll
            for (int od = 0; od < 16; od++) {
                sq0 += u0[od] * u0[od];
                sq1 += u1[od] * u1[od];
            }
            float f0 = squash_factor(sq0), f1 = squash_factor(sq1);
            float b0 = 0.f, b1 = 0.f;
            float t0[16], t1[16];

#pragma unroll
            for (int it = 0; it < 2; it++) {
                float w0 = f0 * sigmoidf_(b0), w1 = f1 * sigmoidf_(b1);
#pragma unroll
                for (int od = 0; od < 16; od++) {
                    t0[od] = w0 * u0[od];
                    t1[od] = w1 * u1[od];
                }
#pragma unroll
                for (int d = 4; d <= 16; d <<= 1) {
#pragma unroll
                    for (int od = 0; od < 16; od++) {
                        t0[od] += __shfl_xor_sync(0xFFFFFFFFu, t0[od], d);
                        t1[od] += __shfl_xor_sync(0xFFFFFFFFu, t1[od], d);
                    }
                }
                float gs0 = 0.f, gs1 = 0.f, dot0 = 0.f, dot1 = 0.f;
#pragma unroll
                for (int od = 0; od < 16; od++) {
                    gs0 += t0[od] * t0[od];
                    gs1 += t1[od] * t1[od];
                    dot0 += u0[od] * t0[od];
                    dot1 += u1[od] * t1[od];
                }
                b0 += f0 * squash_factor(gs0) * dot0;
                b1 += f1 * squash_factor(gs1) * dot1;
            }
            {
                float w0 = sigmoidf_(b0), w1 = sigmoidf_(b1);
#pragma unroll
                for (int od = 0; od < 16; od++) {
                    t0[od] = w0 * u0[od];
                    t1[od] = w1 * u1[od];
                }
#pragma unroll
                for (int d = 4; d <= 16; d <<= 1) {
#pragma unroll
                    for (int od = 0; od < 16; od++) {
                        t0[od] += __shfl_xor_sync(0xFFFFFFFFu, t0[od], d);
                        t1[od] += __shfl_xor_sync(0xFFFFFFFFu, t1[od], d);
                    }
                }
            }
            float a0 = 0.f, a1 = 0.f, c0v = 0.f, c1v = 0.f;
#pragma unroll
            for (int k = 0; k < 8; k++) {
                if (icb == k) {
                    a0 = t0[2 * k]; a1 = t0[2 * k + 1];
                    c0v = t1[2 * k]; c1v = t1[2 * k + 1];
                }
            }
            float* sp = g_s + (size_t)pixelb * 128 + qq * 32 + 2 * icb;
            *(float2*)sp = make_float2(a0, a1);
            *(float2*)(sp + 16) = make_float2(c0v, c1v);
        }
    }
}

// ================= K5a/K5b: mean over HW (two-stage, deterministic) ============
__global__ void __launch_bounds__(128) k5a() {
    int id = blockIdx.x;
    int chunk = id & 127, b = id >> 7;
    int t = threadIdx.x;
    float acc = 0.f;
    const float* sp = g_s + ((size_t)(b * 4096 + chunk * 32)) * 128 + t;
    for (int p = 0; p < 32; p++) acc += sp[(size_t)p * 128];
    g_part[(b * 128 + chunk) * 128 + t] = acc;
}
__global__ void __launch_bounds__(128) k5b() {
    int b = blockIdx.x, t = threadIdx.x;
    float acc = 0.f;
    for (int c = 0; c < 128; c++) acc += g_part[(b * 128 + c) * 128 + t];
    g_meanhw[b * 128 + t] = acc * (1.0f / 4096.0f);
}

// ================= K6: avg + per-(b,oc) mean/std over HW =======================
__global__ void __launch_bounds__(256) k6() {
    int b = blockIdx.x >> 3, oc = blockIdx.x & 7;
    int t = threadIdx.x;
    __shared__ float mh[16];
    __shared__ double red[512];
    if (t < 16) mh[t] = g_meanhw[b * 128 + oc * 16 + t];
    __syncthreads();
    float mhl[16];
#pragma unroll
    for (int od = 0; od < 16; od++) mhl[od] = mh[od];

    double sum = 0.0, ssum = 0.0;
    for (int p = t; p < 4096; p += 256) {
        const float4* sp =
            (const float4*)(g_s + ((size_t)(b * 4096 + p)) * 128 + oc * 16);
        float a = 0.f;
#pragma unroll
        for (int j = 0; j < 4; j++) {
            float4 v = sp[j];
            a += v.x * mhl[4 * j] + v.y * mhl[4 * j + 1] + v.z * mhl[4 * j + 2] +
                 v.w * mhl[4 * j + 3];
        }
        g_avg[(b * 8 + oc) * 4096 + p] = a;
        sum += (double)a;
        ssum += (double)a * (double)a;
    }
    red[t] = sum;
    red[256 + t] = ssum;
    __syncthreads();
    for (int st = 128; st > 0; st >>= 1) {
        if (t < st) {
            red[t] += red[t + st];
            red[256 + t] += red[256 + t + st];
        }
        __syncthreads();
    }
    if (t == 0) {
        double S = red[0], Q = red[256];
        double m = S / 4096.0;
        double var = (Q - S * m) / 4095.0;
        if (var < 0.0) var = 0.0;
        g_stats[(b * 8 + oc) * 2] = (float)m;
        g_stats[(b * 8 + oc) * 2 + 1] = (float)(sqrt(var) + 1e-6);
    }
}

// ================= K7: out = s*sigmoid(norm*aw+ab) + x (planar) ===============
__global__ void __launch_bounds__(256) k7(const float* __restrict__ x,
                                          const float* __restrict__ aw,
                                          const float* __restrict__ ab,
                                          float* __restrict__ out) {
    int id = blockIdx.x;
    int tile = id & 63, b = id >> 6;
    int pixbase = tile * 64;
    __shared__ float ssh[64 * 129];
    __shared__ float stm[8], sts[8], awl[8], abl[8];
    int t = threadIdx.x;
    if (t < 8) {
        stm[t] = g_stats[(b * 8 + t) * 2];
        sts[t] = g_stats[(b * 8 + t) * 2 + 1];
        awl[t] = aw[t];
        abl[t] = ab[t];
    }
    for (int idx = t; idx < 8192; idx += 256) {
        int p = idx >> 7, c = idx & 127;
        ssh[p * 129 + c] = g_s[((size_t)(b * 4096 + pixbase + p)) * 128 + c];
    }
    __syncthreads();
    int cs = t >> 6, p = t & 63;
    for (int k = 0; k < 32; k++) {
        int c = k * 4 + cs;
        int oc = c >> 4;
        float a = g_avg[(b * 8 + oc) * 4096 + pixbase + p];
        float tn = (a - stm[oc]) / sts[oc] * awl[oc] + abl[oc];
        float sg = sigmoidf_(tn);
        size_t o = ((size_t)(b * 128 + c)) * 4096 + pixbase + p;
        out[o] = ssh[p * 129 + c] * sg + x[o];
    }
}

// ================= launcher =================
extern "C" void kernel_launch(void* const* d_in, const int* in_sizes, int n_in,
                              void* d_out, int out_size) {
    const float* x = (const float*)d_in[0];
    const float* w1 = (const float*)d_in[1];
    const float* b1 = (const float*)d_in[2];
    const float* w2 = (const float*)d_in[3];
    const float* b2 = (const float*)d_in[4];
    const float* w3 = (const float*)d_in[5];
    const float* b3 = (const float*)d_in[6];
    const float* aw = (const float*)d_in[7];
    const float* ab = (const float*)d_in[8];
    float* out = (float*)d_out;

    static int smem_set = 0;
    if (!smem_set) {
        cudaFuncSetAttribute(k2_conv3, cudaFuncAttributeMaxDynamicSharedMemorySize,
                             SMEM_K2);
        cudaFuncSetAttribute(k34_fused, cudaFuncAttributeMaxDynamicSharedMemorySize,
                             SMEM34);
        smem_set = 1;
    }

    k1_conv1<<<512, 256>>>(x, w1, b1);
    kw3t<<<128, 256>>>(w3);
    k2_conv3<<<1024, 256, SMEM_K2>>>(w2, b2);
    k34_fused<<<1024, 256, SMEM34>>>(b3);       // <- ncu capture slot (#4)
    k5a<<<1024, 128>>>();
    k5b<<<8, 128>>>();
    k6<<<64, 256>>>();
    k7<<<512, 256>>>(x, aw, ab, out);
}